// round 13
// baseline (speedup 1.0000x reference)
#include <cuda_runtime.h>

#define HH 2048
#define WW 2048
#define NB 1024

#define SEGW 128          // pixels per warp (x segment)
#define BT   256          // threads per block = 8 warps

// ---------------------------------------------------------------------------
// Warp-autonomous: each warp owns one 128x1 row segment. No smem, no barriers.
// Scan raw boxes descending (paint order), 32/step: lane tests one box for
// validity + y-containment + x-overlap with the segment; ballot; walk hit
// lanes in ffs order (= descending paint index), shfl-broadcast packed
// x-bounds, capture per-pixel first hits; __all_sync early exit once all
// 128 px are resolved.
// ---------------------------------------------------------------------------
__global__ void __launch_bounds__(BT) paint_kernel(const float* __restrict__ boxes,
                                                   float* __restrict__ out) {
    const int lane = threadIdx.x & 31;
    const int wid  = threadIdx.x >> 5;

    const int tx0 = blockIdx.x * SEGW;            // segment start (warp-uniform)
    const int y   = blockIdx.y * (BT / 32) + wid; // row (warp-uniform)
    const int x0  = tx0 + lane * 4;               // this lane's 4 pixels

    int j0 = -1, j1 = -1, j2 = -1, j3 = -1;
    bool alldone = false;

    for (int base = 0; base < NB && !alldone; base += 32) {
        const int i = (NB - 1) - base - lane;      // lane 0 = highest index
        // coalesced 16B loads of 32 consecutive boxes (L1/L2 resident)
        float4 v = *(const float4*)(boxes + 4 * i);
        // match reference: truncate toward zero, then clamp
        int y1 = max(0,  (int)(v.x * (float)HH));
        int x1 = max(0,  (int)(v.y * (float)WW));
        int y2 = min(HH, (int)(v.z * (float)HH));
        int x2 = min(WW, (int)(v.w * (float)WW));

        // valid (y1<y2 && x1<x2) + contains row y + x-overlaps the segment.
        // NOTE: the unsigned y-containment trick requires y1 < y2 explicitly,
        // otherwise (unsigned)(y2-y1) wraps and invalid boxes match.
        bool hit = (y1 < y2) && (x1 < x2) &&
                   ((unsigned)(y - y1) < (unsigned)(y2 - y1)) &&
                   (x1 < tx0 + SEGW) && (x2 > tx0);
        unsigned pk = (unsigned)x1 | ((unsigned)x2 << 16);  // pack x-bounds

        unsigned m = __ballot_sync(0xffffffffu, hit);       // warp-uniform

        while (m) {                                // ffs = descending paint idx
            int k = __ffs(m) - 1;
            m &= m - 1;
            unsigned bx = __shfl_sync(0xffffffffu, pk, k);
            int bi      = __shfl_sync(0xffffffffu, i,  k);
            int rel = x0 - (int)(bx & 0xffffu);
            unsigned w = (bx >> 16) - (bx & 0xffffu);
            if (j0 < 0 && (unsigned)(rel    ) < w) j0 = bi;
            if (j1 < 0 && (unsigned)(rel + 1) < w) j1 = bi;
            if (j2 < 0 && (unsigned)(rel + 2) < w) j2 = bi;
            if (j3 < 0 && (unsigned)(rel + 3) < w) j3 = bi;
            if (__all_sync(0xffffffffu, (j0 | j1 | j2 | j3) >= 0)) {
                alldone = true;                    // warp-uniform
                break;
            }
        }
    }

    // Gather values for the winning boxes straight from the global list
    // (16 KB, L1-resident; mostly-uniform indices within a warp).
    float4 z  = make_float4(0.f, 0.f, 0.f, 0.f);
    float4 v0 = (j0 >= 0) ? *(const float4*)(boxes + 4 * j0) : z;
    float4 v1 = (j1 >= 0) ? *(const float4*)(boxes + 4 * j1) : z;
    float4 v2 = (j2 >= 0) ? *(const float4*)(boxes + 4 * j2) : z;
    float4 v3 = (j3 >= 0) ? *(const float4*)(boxes + 4 * j3) : z;

    float4 c0 = make_float4(j0 >= 0 ? 1.f : 0.f,
                            j1 >= 0 ? 1.f : 0.f,
                            j2 >= 0 ? 1.f : 0.f,
                            j3 >= 0 ? 1.f : 0.f);
    float4 c1 = make_float4(v0.x, v1.x, v2.x, v3.x);
    float4 c2 = make_float4(v0.y, v1.y, v2.y, v3.y);
    float4 c3 = make_float4(v0.z, v1.z, v2.z, v3.z);
    float4 c4 = make_float4(v0.w, v1.w, v2.w, v3.w);

    const size_t HWsz = (size_t)HH * (size_t)WW;
    size_t base = (size_t)y * WW + (size_t)x0;
    *(float4*)(out + 0 * HWsz + base) = c0;
    *(float4*)(out + 1 * HWsz + base) = c1;
    *(float4*)(out + 2 * HWsz + base) = c2;
    *(float4*)(out + 3 * HWsz + base) = c3;
    *(float4*)(out + 4 * HWsz + base) = c4;
}

extern "C" void kernel_launch(void* const* d_in, const int* in_sizes, int n_in,
                              void* d_out, int out_size) {
    const float* boxes = (const float*)d_in[0];
    float* out = (float*)d_out;

    dim3 block(BT);                            // 256 threads = 8 warps
    dim3 grid(WW / SEGW, HH / (BT / 32));      // (16, 256) = 4096 blocks
    paint_kernel<<<grid, block>>>(boxes, out);
}